// round 5
// baseline (speedup 1.0000x reference)
#include <cuda_runtime.h>
#include <cuda_bf16.h>
#include <cstdint>

// Problem constants
#define BB 2
#define TT 1024
#define CC 768
#define HH 12
#define DH 64
#define LL 4
#define HID 3072
#define VV 32000
#define BT (BB*TT)          // 2048
#define QKVN (3*CC)         // 2304

// ---------------- scratch (device globals; no cudaMalloc allowed) ----------
__device__ float g_x[BT*CC];          // residual stream
__device__ float g_h[BT*CC];          // layernorm output / rounded x copy
__device__ float g_qkv[BT*QKVN];      // fused qkv output
__device__ float g_attn[BT*CC];       // attention output (concat heads)
__device__ float g_hid[BT*HID];       // MLP hidden
__device__ float g_wqkv[LL*QKVN*CC];  // packed+rounded qkv weights, [n][k]
__device__ float g_wproj[LL*CC*CC];   // transposed+rounded [n][k]
__device__ float g_w1[LL*HID*CC];     // transposed+rounded [n][k]
__device__ float g_w2[LL*CC*HID];     // transposed+rounded [n][k]
__device__ float g_wlm[VV*CC];        // transposed+rounded [n][k]
__device__ float g_rowloss[BT];       // per-row -logp[target]

__device__ __forceinline__ uint32_t f2tf32(float f) {
    uint32_t u;
    asm("cvt.rna.tf32.f32 %0, %1;" : "=r"(u) : "f"(f));
    return u;
}
__device__ __forceinline__ float tf32r(float f) {
    return __uint_as_float(f2tf32(f));
}

// ---------------- qkv weight pack+transpose: W[L,H,C,DH] -> [L][3C][C] -----
__global__ void __launch_bounds__(256)
pack_qkv_t_kernel(const float* __restrict__ Wq, const float* __restrict__ Wk,
                  const float* __restrict__ Wv) {
    __shared__ float s[32][33];
    const int l   = blockIdx.z;
    const int sel = blockIdx.y / HH;
    const int h   = blockIdx.y % HH;
    const int d0  = (blockIdx.x & 1) * 32;
    const int k0  = (blockIdx.x >> 1) * 32;
    const float* W = (sel == 0) ? Wq : (sel == 1) ? Wk : Wv;
    const float* src = W + (((long)l*HH + h)*CC)*DH;
    const int tx = threadIdx.x, ty = threadIdx.y;
    #pragma unroll
    for (int i = 0; i < 4; i++) {
        int r = ty + i*8;
        s[r][tx] = src[(long)(k0 + r)*DH + d0 + tx];
    }
    __syncthreads();
    float* dst = g_wqkv + ((long)l*QKVN + sel*CC + h*DH + d0)*CC + k0;
    #pragma unroll
    for (int i = 0; i < 4; i++) {
        int r = ty + i*8;
        dst[(long)r*CC + tx] = tf32r(s[tx][r]);
    }
}

// ---------------- generic transpose+round: src[z][R][Cn] -> dst[z][Cn][R] --
__global__ void __launch_bounds__(256)
transpose_round_kernel(const float* __restrict__ src, float* __restrict__ dst,
                       int R, int Cn) {
    __shared__ float s[32][33];
    const int c0 = blockIdx.x * 32;
    const int r0 = blockIdx.y * 32;
    const long zo = (long)blockIdx.z * R * Cn;
    const int tx = threadIdx.x, ty = threadIdx.y;
    #pragma unroll
    for (int i = 0; i < 4; i++) {
        int r = ty + i*8;
        s[r][tx] = src[zo + (long)(r0 + r)*Cn + c0 + tx];
    }
    __syncthreads();
    #pragma unroll
    for (int i = 0; i < 4; i++) {
        int r = ty + i*8;
        dst[zo + (long)(c0 + r)*R + r0 + tx] = tf32r(s[tx][r]);
    }
}

// ---------------- generic tf32 round-copy ----------------------------------
__global__ void round_copy_kernel(const float* __restrict__ src,
                                  float* __restrict__ dst, long n) {
    for (long i = (long)blockIdx.x * blockDim.x + threadIdx.x; i < n;
         i += (long)gridDim.x * blockDim.x)
        dst[i] = tf32r(src[i]);
}

// ---------------- embedding ------------------------------------------------
__global__ void embed_kernel(const int* __restrict__ idx,
                             const float* __restrict__ tok,
                             const float* __restrict__ pos) {
    int i = blockIdx.x * blockDim.x + threadIdx.x;
    if (i >= BT*CC) return;
    int c = i % CC;
    int bt = i / CC;
    int t = bt % TT;
    g_x[i] = tok[(long)idx[bt]*CC + c] + pos[(long)t*CC + c];
}

// ---------------- layernorm (rounded output) -------------------------------
__global__ void layernorm_kernel(const float* __restrict__ x,
                                 const float* __restrict__ g,
                                 const float* __restrict__ b,
                                 float* __restrict__ y) {
    __shared__ float rs[256], rs2[256];
    int row = blockIdx.x;
    const float* xr = x + (long)row*CC;
    float s = 0.f, s2 = 0.f;
    for (int c = threadIdx.x; c < CC; c += 256) {
        float v = xr[c];
        s += v; s2 += v*v;
    }
    rs[threadIdx.x] = s; rs2[threadIdx.x] = s2;
    __syncthreads();
    for (int o = 128; o > 0; o >>= 1) {
        if (threadIdx.x < o) {
            rs[threadIdx.x]  += rs[threadIdx.x + o];
            rs2[threadIdx.x] += rs2[threadIdx.x + o];
        }
        __syncthreads();
    }
    float mean = rs[0] * (1.f/CC);
    float var  = rs2[0] * (1.f/CC) - mean*mean;
    float inv  = rsqrtf(var + 1e-5f);
    for (int c = threadIdx.x; c < CC; c += 256) {
        y[(long)row*CC + c] = tf32r((xr[c] - mean) * inv * g[c] + b[c]);
    }
}

// =================== TF32 mma.sync GEMM, ldmatrix + cp.async ===============
// C[M,N] = A[M,K] * Bt[N,K]^T  (+bias)(+res)(relu)(round). Pre-rounded I/O.
// BM=BN=128, BK=16, 3-stage cp.async. 256 threads = 8 warps (4Mx2N),
// warp tile 32x64. Fragments via ldmatrix.m8n8.x4.b16 (b32 view).
// Row stride 20 floats: cp.async dst 16B-aligned (80B rows), LDSM rows hit
// distinct banks (20*r mod 32 distinct for r=0..7).
#define RS 20
#define TILEF (128*RS)          // floats per tensor per stage
#define GSTAGES 3
#define GSMEM_TOT (GSTAGES*2*TILEF*4)   // 61440 B

#define CP16(dst, src) asm volatile("cp.async.cg.shared.global [%0], [%1], 16;" :: "r"(dst), "l"(src))

__device__ __forceinline__ void ldsm4(uint32_t addr, uint32_t& r0, uint32_t& r1,
                                      uint32_t& r2, uint32_t& r3) {
    asm volatile("ldmatrix.sync.aligned.m8n8.x4.shared.b16 {%0,%1,%2,%3}, [%4];"
                 : "=r"(r0), "=r"(r1), "=r"(r2), "=r"(r3) : "r"(addr));
}

template<bool BIAS, bool RELU, bool RES, bool ROUND>
__global__ void __launch_bounds__(256)
gemm_tf32_kernel(const float* __restrict__ A, const float* __restrict__ Bt,
                 const float* __restrict__ bias, const float* __restrict__ res,
                 float* __restrict__ C, int M, int N, int K) {
    extern __shared__ float smem[];
    uint32_t sb;
    asm("{ .reg .u64 t; cvta.to.shared.u64 t, %1; cvt.u32.u64 %0, t; }"
        : "=r"(sb) : "l"(smem));
    const int tid  = threadIdx.x;
    const int wid  = tid >> 5;
    const int lane = tid & 31;
    const int warpM = wid & 3;
    const int warpN = wid >> 2;
    const int gr = lane >> 2;
    const int gc = lane & 3;
    const int m0 = blockIdx.y * 128;
    const int n0 = blockIdx.x * 128;

    float acc[2][8][4];
    #pragma unroll
    for (int mi = 0; mi < 2; mi++)
        #pragma unroll
        for (int ni = 0; ni < 8; ni++)
            #pragma unroll
            for (int j = 0; j < 4; j++) acc[mi][ni][j] = 0.f;

    // staging: each thread loads one 32B piece (2x cp.async.16) per tensor
    const int ldRow = tid >> 1;              // 0..127
    const int ldCol = (tid & 1) * 8;         // float offset 0 or 8
    const float* Ag0 = A  + (long)(m0 + ldRow)*K + ldCol;
    const float* Bg0 = Bt + (long)(n0 + ldRow)*K + ldCol;
    const uint32_t sOffAB = (uint32_t)(ldRow*RS + ldCol)*4;

    // ldmatrix per-lane addressing
    const int sel = lane >> 3;
    const int aRowSel = (sel & 1)*8 + (lane & 7);
    const int aColSel = (sel >> 1)*4;
    const int bRowSel = (sel >> 1)*8 + (lane & 7);
    const int bColSel = (sel & 1)*4;

    const int nIter = K >> 4;

    #define GISSUE(it, stg) do {                                               \
        const float* Ag = Ag0 + ((it) << 4);                                   \
        const float* Bg = Bg0 + ((it) << 4);                                   \
        uint32_t da = sb + (stg)*(2*TILEF*4) + sOffAB;                         \
        uint32_t db = da + TILEF*4;                                            \
        CP16(da, Ag);  CP16(da + 16, Ag + 4);                                  \
        CP16(db, Bg);  CP16(db + 16, Bg + 4);                                  \
        asm volatile("cp.async.commit_group;");                                \
    } while (0)

    GISSUE(0, 0);
    GISSUE(1, 1);

    for (int it = 0; it < nIter; it++) {
        const int stg = it % GSTAGES;
        if (it + 1 < nIter) asm volatile("cp.async.wait_group 1;");
        else                asm volatile("cp.async.wait_group 0;");
        __syncthreads();
        if (it + 2 < nIter) GISSUE(it + 2, (it + 2) % GSTAGES);

        const uint32_t sA = sb + stg*(2*TILEF*4);
        const uint32_t sB = sA + TILEF*4;

        #pragma unroll
        for (int kc = 0; kc < 16; kc += 8) {
            uint32_t af[2][4];
            #pragma unroll
            for (int mi = 0; mi < 2; mi++) {
                uint32_t addr = sA +
                    (uint32_t)((warpM*32 + mi*16 + aRowSel)*RS + kc + aColSel)*4;
                ldsm4(addr, af[mi][0], af[mi][1], af[mi][2], af[mi][3]);
            }
            uint32_t bf[8][2];
            #pragma unroll
            for (int nip = 0; nip < 4; nip++) {
                uint32_t addr = sB +
                    (uint32_t)((warpN*64 + nip*16 + bRowSel)*RS + kc + bColSel)*4;
                ldsm4(addr, bf[2*nip][0], bf[2*nip][1],
                            bf[2*nip+1][0], bf[2*nip+1][1]);
            }
            #pragma unroll
            for (int mi = 0; mi < 2; mi++)
                #pragma unroll
                for (int ni = 0; ni < 8; ni++)
                    asm volatile(
                        "mma.sync.aligned.m16n8k8.row.col.f32.tf32.tf32.f32 "
                        "{%0,%1,%2,%3},{%4,%5,%6,%7},{%8,%9},{%0,%1,%2,%3};"
                        : "+f"(acc[mi][ni][0]), "+f"(acc[mi][ni][1]),
                          "+f"(acc[mi][ni][2]), "+f"(acc[mi][ni][3])
                        : "r"(af[mi][0]), "r"(af[mi][1]),
                          "r"(af[mi][2]), "r"(af[mi][3]),
                          "r"(bf[ni][0]), "r"(bf[ni][1]));
        }
    }
    #undef GISSUE

    // epilogue: c0,c1 at (row=gr, col=2gc..+1); c2,c3 at row gr+8
    #pragma unroll
    for (int mi = 0; mi < 2; mi++) {
        #pragma unroll
        for (int rr = 0; rr < 2; rr++) {
            long row = m0 + warpM*32 + mi*16 + gr + rr*8;
            #pragma unroll
            for (int ni = 0; ni < 8; ni++) {
                int col = n0 + warpN*64 + ni*8 + gc*2;
                float v0 = acc[mi][ni][rr*2+0];
                float v1 = acc[mi][ni][rr*2+1];
                if (BIAS) { v0 += bias[col]; v1 += bias[col+1]; }
                if (RES)  {
                    float2 rv = *(const float2*)(res + row*N + col);
                    v0 += rv.x; v1 += rv.y;
                }
                if (RELU) { v0 = fmaxf(v0, 0.f); v1 = fmaxf(v1, 0.f); }
                if (ROUND){ v0 = tf32r(v0); v1 = tf32r(v1); }
                float2 ov; ov.x = v0; ov.y = v1;
                *(float2*)(C + row*N + col) = ov;
            }
        }
    }
}

// ---------------- flash attention, 2-way split-K ---------------------------
#define TQ 64
#define TS 16
__global__ void __launch_bounds__(128)
flash_attn_kernel(const float* __restrict__ qkv, float* __restrict__ out) {
    __shared__ float KV[2][2][TS*DH];   // [k/v][half][s*DH+d]
    __shared__ float ml[2][TQ];
    const int q0 = (gridDim.x - 1 - blockIdx.x) * TQ;  // longest first
    const int bh = blockIdx.y;
    const int b  = bh / HH;
    const int h  = bh % HH;
    const int tid  = threadIdx.x;
    const int tq   = tid & 63;
    const int half = tid >> 6;
    const int t = q0 + tq;
    const float* base = qkv + (long)b*TT*QKVN;

    float q[DH];
    {
        const float4* qr = (const float4*)(base + (long)t*QKVN + h*DH);
        #pragma unroll
        for (int j = 0; j < DH/4; j++) {
            float4 v = qr[j];
            q[4*j+0] = v.x; q[4*j+1] = v.y; q[4*j+2] = v.z; q[4*j+3] = v.w;
        }
    }
    float acc[DH];
    #pragma unroll
    for (int j = 0; j < DH; j++) acc[j] = 0.f;
    float m = -1e30f, l = 0.f;

    const int nT = (q0 + TQ) / TS;
    const int nHalf = nT >> 1;
    const int tile0 = half * nHalf;

    for (int jt = 0; jt < nHalf; jt++) {
        const int s0 = (tile0 + jt) * TS;
        __syncthreads();
        #pragma unroll
        for (int i = 0; i < 4; i++) {
            int idx = tq + i*64;
            int s  = idx >> 4;
            int d4 = (idx & 15) << 2;
            const float* kp = base + (long)(s0+s)*QKVN + CC + h*DH + d4;
            *(float4*)&KV[0][half][s*DH + d4] = *(const float4*)kp;
            *(float4*)&KV[1][half][s*DH + d4] = *(const float4*)(kp + CC);
        }
        __syncthreads();

        float sc[TS];
        float tmax = -1e30f;
        #pragma unroll
        for (int s = 0; s < TS; s++) {
            float d0 = 0.f, d1 = 0.f, d2 = 0.f, d3 = 0.f;
            const float* kr = &KV[0][half][s*DH];
            #pragma unroll
            for (int j = 0; j < DH; j += 4) {
                d0 += q[j+0] * kr[j+0];
                d1 += q[j+1] * kr[j+1];
                d2 += q[j+2] * kr[j+2];
                d3 += q[j+3] * kr[j+3];
            }
            float d = (d0 + d1) + (d2 + d3);
            sc[s] = (s0 + s <= t) ? d * 0.125f : -1e30f;
            tmax = fmaxf(tmax, sc[s]);
        }
        if (tmax > -1e29f) {
            float m_new = fmaxf(m, tmax);
            float alpha = __expf(m - m_new);
            l *= alpha;
            #pragma unroll
            for (int j = 0; j < DH; j++) acc[j] *= alpha;
            #pragma unroll
            for (int s = 0; s < TS; s++) {
                float p = (sc[s] > -1e29f) ? __expf(sc[s] - m_new) : 0.f;
                l += p;
                const float* vr = &KV[1][half][s*DH];
                #pragma unroll
                for (int j = 0; j < DH; j++) acc[j] += p * vr[j];
            }
            m = m_new;
        }
    }

    __syncthreads();
    float* xch = (float*)KV;
    if (half == 1) {
        ml[0][tq] = m; ml[1][tq] = l;
        #pragma unroll
        for (int j = 0; j < DH; j++)
            xch[tq*DH + ((j + tq) & 63)] = acc[j];
    }
    __syncthreads();
    if (half == 0) {
        float m1 = ml[0][tq], l1 = ml[1][tq];
        float ms = fmaxf(m, m1);
        float a0 = __expf(m - ms);
        float a1 = __expf(m1 - ms);
        float inv = 1.0f / (l*a0 + l1*a1);
        float* o = out + ((long)b*TT + t)*CC + h*DH;
        #pragma unroll
        for (int j = 0; j < DH; j += 4) {
            float4 v;
            v.x = tf32r((acc[j+0]*a0 + xch[tq*DH + ((j+0+tq)&63)]*a1) * inv);
            v.y = tf32r((acc[j+1]*a0 + xch[tq*DH + ((j+1+tq)&63)]*a1) * inv);
            v.z = tf32r((acc[j+2]*a0 + xch[tq*DH + ((j+2+tq)&63)]*a1) * inv);
            v.w = tf32r((acc[j+3]*a0 + xch[tq*DH + ((j+3+tq)&63)]*a1) * inv);
            *(float4*)(o + j) = v;
        }
    }
}

// ---------------- cross-entropy: single-pass online softmax ----------------
__global__ void loss_rows_kernel(const float* __restrict__ logits,
                                 const int* __restrict__ targets) {
    __shared__ float sm[256], ss[256];
    const int row = blockIdx.x;
    const float* lr = logits + (long)row*VV;
    float m = -1e30f, s = 0.f;
    for (int c = threadIdx.x; c < VV; c += 256) {
        float v = lr[c];
        if (v <= m) s += __expf(v - m);
        else { s = s*__expf(m - v) + 1.f; m = v; }
    }
    sm[threadIdx.x] = m; ss[threadIdx.x] = s;
    __syncthreads();
    for (int o = 128; o > 0; o >>= 1) {
        if (threadIdx.x < o) {
            float m2 = sm[threadIdx.x+o], s2 = ss[threadIdx.x+o];
            float mm = fmaxf(sm[threadIdx.x], m2);
            ss[threadIdx.x] = ss[threadIdx.x]*__expf(sm[threadIdx.x]-mm)
                            + s2*__expf(m2-mm);
            sm[threadIdx.x] = mm;
        }
        __syncthreads();
    }
    if (threadIdx.x == 0) {
        float lse = sm[0] + logf(ss[0]);
        g_rowloss[row] = lse - lr[targets[row]];
    }
}

__global__ void loss_reduce_kernel(float* __restrict__ out) {
    __shared__ float red[256];
    float s = 0.f;
    for (int i = threadIdx.x; i < BT; i += 256) s += g_rowloss[i];
    red[threadIdx.x] = s; __syncthreads();
    for (int o = 128; o > 0; o >>= 1) {
        if (threadIdx.x < o) red[threadIdx.x] += red[threadIdx.x+o];
        __syncthreads();
    }
    if (threadIdx.x == 0) *out = red[0] * (1.0f/BT);
}

// ---------------- driver ----------------------------------------------------
extern "C" void kernel_launch(void* const* d_in, const int* in_sizes, int n_in,
                              void* d_out, int out_size) {
    const int*   idx     = (const int*)  d_in[0];
    const int*   targets = (const int*)  d_in[1];
    const float* tok_emb = (const float*)d_in[2];
    const float* pos_emb = (const float*)d_in[3];
    const float* Wq      = (const float*)d_in[4];
    const float* Wk      = (const float*)d_in[5];
    const float* Wv      = (const float*)d_in[6];
    const float* Wproj   = (const float*)d_in[7];
    const float* bproj   = (const float*)d_in[8];
    const float* ln1_g   = (const float*)d_in[9];
    const float* ln1_b   = (const float*)d_in[10];
    const float* ln2_g   = (const float*)d_in[11];
    const float* ln2_b   = (const float*)d_in[12];
    const float* W1      = (const float*)d_in[13];
    const float* b1      = (const float*)d_in[14];
    const float* W2      = (const float*)d_in[15];
    const float* b2      = (const float*)d_in[16];
    const float* Wlm     = (const float*)d_in[17];
    const float* blm     = (const float*)d_in[18];
    float* out = (float*)d_out;

    float* xp;    cudaGetSymbolAddress((void**)&xp,    g_x);
    float* hp;    cudaGetSymbolAddress((void**)&hp,    g_h);
    float* qkvp;  cudaGetSymbolAddress((void**)&qkvp,  g_qkv);
    float* attnp; cudaGetSymbolAddress((void**)&attnp, g_attn);
    float* hidp;  cudaGetSymbolAddress((void**)&hidp,  g_hid);
    float* wqkvp; cudaGetSymbolAddress((void**)&wqkvp, g_wqkv);
    float* wprojp;cudaGetSymbolAddress((void**)&wprojp,g_wproj);
    float* w1p;   cudaGetSymbolAddress((void**)&w1p,   g_w1);
    float* w2p;   cudaGetSymbolAddress((void**)&w2p,   g_w2);
    float* wlmp;  cudaGetSymbolAddress((void**)&wlmp,  g_wlm);

    cudaFuncSetAttribute(gemm_tf32_kernel<false,false,false,false>,
                         cudaFuncAttributeMaxDynamicSharedMemorySize, GSMEM_TOT);
    cudaFuncSetAttribute(gemm_tf32_kernel<true,false,true,false>,
                         cudaFuncAttributeMaxDynamicSharedMemorySize, GSMEM_TOT);
    cudaFuncSetAttribute(gemm_tf32_kernel<true,true,false,true>,
                         cudaFuncAttributeMaxDynamicSharedMemorySize, GSMEM_TOT);
    cudaFuncSetAttribute(gemm_tf32_kernel<true,false,false,false>,
                         cudaFuncAttributeMaxDynamicSharedMemorySize, GSMEM_TOT);

    dim3 t32x8(32, 8);
    pack_qkv_t_kernel<<<dim3(48, 3*HH, LL), t32x8>>>(Wq, Wk, Wv);
    transpose_round_kernel<<<dim3(CC/32,  CC/32,  LL), t32x8>>>(Wproj, wprojp, CC,  CC);
    transpose_round_kernel<<<dim3(HID/32, CC/32,  LL), t32x8>>>(W1,    w1p,    CC,  HID);
    transpose_round_kernel<<<dim3(CC/32,  HID/32, LL), t32x8>>>(W2,    w2p,    HID, CC);
    transpose_round_kernel<<<dim3(VV/32,  CC/32,  1 ), t32x8>>>(Wlm,   wlmp,   CC,  VV);
    embed_kernel<<<(BT*CC + 255)/256, 256>>>(idx, tok_emb, pos_emb);

    for (int l = 0; l < LL; l++) {
        layernorm_kernel<<<BT, 256>>>(xp, ln1_g + l*CC, ln1_b + l*CC, hp);

        // qkv = h @ Wqkv[l]
        gemm_tf32_kernel<false,false,false,false>
            <<<dim3(QKVN/128, BT/128), 256, GSMEM_TOT>>>(
            hp, wqkvp + (long)l*QKVN*CC, nullptr, nullptr, qkvp, BT, QKVN, CC);

        flash_attn_kernel<<<dim3(TT/TQ, BB*HH), 128>>>(qkvp, attnp);

        // x = x + attn @ Wproj[l] + bproj[l]
        gemm_tf32_kernel<true,false,true,false>
            <<<dim3(CC/128, BT/128), 256, GSMEM_TOT>>>(
            attnp, wprojp + (long)l*CC*CC, bproj + l*CC, xp, xp, BT, CC, CC);

        layernorm_kernel<<<BT, 256>>>(xp, ln2_g + l*CC, ln2_b + l*CC, hp);

        // hid = relu(h @ W1[l] + b1[l])  (rounded: feeds next GEMM)
        gemm_tf32_kernel<true,true,false,true>
            <<<dim3(HID/128, BT/128), 256, GSMEM_TOT>>>(
            hp, w1p + (long)l*HID*CC, b1 + (long)l*HID, nullptr, hidp, BT, HID, CC);

        // x = x + hid @ W2[l] + b2[l]
        gemm_tf32_kernel<true,false,true,false>
            <<<dim3(CC/128, BT/128), 256, GSMEM_TOT>>>(
            hidp, w2p + (long)l*CC*HID, b2 + l*CC, xp, xp, BT, CC, HID);
    }

    round_copy_kernel<<<2048, 256>>>(xp, hp, (long)BT*CC);

    // logits = x @ Wlm + blm -> d_out
    gemm_tf32_kernel<true,false,false,false>
        <<<dim3(VV/128, BT/128), 256, GSMEM_TOT>>>(
        hp, wlmp, blm, nullptr, out, BT, VV, CC);

    loss_rows_kernel<<<BT, 256>>>(out, targets);
    if (out_size >= BT*VV + 1) {
        loss_reduce_kernel<<<1, 256>>>(out + (long)BT*VV);
    } else if (out_size == 1) {
        loss_reduce_kernel<<<1, 256>>>(out);
    }
}

// round 6
// speedup vs baseline: 1.2180x; 1.2180x over previous
#include <cuda_runtime.h>
#include <cuda_bf16.h>
#include <cstdint>

// Problem constants
#define BB 2
#define TT 1024
#define CC 768
#define HH 12
#define DH 64
#define LL 4
#define HID 3072
#define VV 32000
#define BT (BB*TT)          // 2048
#define QKVN (3*CC)         // 2304

// ---------------- scratch (device globals; no cudaMalloc allowed) ----------
__device__ float g_x[BT*CC];          // residual stream
__device__ float g_h[BT*CC];          // layernorm output / rounded x copy
__device__ float g_qkv[BT*QKVN];      // fused qkv output
__device__ float g_attn[BT*CC];       // attention output (concat heads)
__device__ float g_hid[BT*HID];       // MLP hidden
__device__ float g_wqkv[LL*CC*QKVN];  // packed+rounded qkv weights [k][n]
__device__ float g_wproj[LL*CC*CC];   // rounded
__device__ float g_w1[LL*CC*HID];     // rounded
__device__ float g_w2[LL*HID*CC];     // rounded
__device__ float g_wlm[CC*VV];        // rounded
__device__ float g_rowloss[BT];       // per-row -logp[target]

__device__ __forceinline__ uint32_t f2tf32(float f) {
    uint32_t u;
    asm("cvt.rna.tf32.f32 %0, %1;" : "=r"(u) : "f"(f));
    return u;
}
__device__ __forceinline__ float tf32r(float f) {
    return __uint_as_float(f2tf32(f));
}

// ---------------- weight packing: Wq/Wk/Wv [L,H,C,DH] -> [L][C][3C] (tf32) -
__global__ void pack_qkv_kernel(const float* __restrict__ Wq,
                                const float* __restrict__ Wk,
                                const float* __restrict__ Wv) {
    const long total = (long)LL * CC * QKVN;
    for (long i = (long)blockIdx.x * blockDim.x + threadIdx.x; i < total;
         i += (long)gridDim.x * blockDim.x) {
        int n = (int)(i % QKVN);
        long r = i / QKVN;
        int k = (int)(r % CC);
        int l = (int)(r / CC);
        const float* W; int nn = n;
        if (n < CC)           { W = Wq; }
        else if (n < 2*CC)    { W = Wk; nn = n - CC; }
        else                  { W = Wv; nn = n - 2*CC; }
        int h = nn >> 6, d = nn & 63;
        g_wqkv[i] = tf32r(W[(((long)l*HH + h)*CC + k)*DH + d]);
    }
}

// ---------------- generic tf32 round-copy ----------------------------------
__global__ void round_copy_kernel(const float* __restrict__ src,
                                  float* __restrict__ dst, long n) {
    for (long i = (long)blockIdx.x * blockDim.x + threadIdx.x; i < n;
         i += (long)gridDim.x * blockDim.x)
        dst[i] = tf32r(src[i]);
}

// ---------------- embedding: x = tok_emb[idx] + pos_emb[:T] ----------------
__global__ void embed_kernel(const int* __restrict__ idx,
                             const float* __restrict__ tok,
                             const float* __restrict__ pos) {
    int i = blockIdx.x * blockDim.x + threadIdx.x;
    if (i >= BT*CC) return;
    int c = i % CC;
    int bt = i / CC;
    int t = bt % TT;
    g_x[i] = tok[(long)idx[bt]*CC + c] + pos[(long)t*CC + c];
}

// ---------------- layernorm (rounded output) -------------------------------
__global__ void layernorm_kernel(const float* __restrict__ x,
                                 const float* __restrict__ g,
                                 const float* __restrict__ b,
                                 float* __restrict__ y) {
    __shared__ float rs[256], rs2[256];
    int row = blockIdx.x;
    const float* xr = x + (long)row*CC;
    float s = 0.f, s2 = 0.f;
    for (int c = threadIdx.x; c < CC; c += 256) {
        float v = xr[c];
        s += v; s2 += v*v;
    }
    rs[threadIdx.x] = s; rs2[threadIdx.x] = s2;
    __syncthreads();
    for (int o = 128; o > 0; o >>= 1) {
        if (threadIdx.x < o) {
            rs[threadIdx.x]  += rs[threadIdx.x + o];
            rs2[threadIdx.x] += rs2[threadIdx.x + o];
        }
        __syncthreads();
    }
    float mean = rs[0] * (1.f/CC);
    float var  = rs2[0] * (1.f/CC) - mean*mean;
    float inv  = rsqrtf(var + 1e-5f);
    for (int c = threadIdx.x; c < CC; c += 256) {
        y[(long)row*CC + c] = tf32r((xr[c] - mean) * inv * g[c] + b[c]);
    }
}

// ---------------- TF32 tensor-core GEMM, cp.async 4-stage pipeline ---------
// Inputs MUST be tf32-pre-rounded fp32 -> mma's internal conversion is exact.
// BM=BN=128, BK=16, 256 threads = 8 warps (4x2), warp tile 32x64.
// Grid: blockIdx.x = M tile (FAST axis -> B-tile reuse in L2), blockIdx.y = N.
#define ASTRIDE 20    // [m][k] padded, conflict-free frags, 16B-aligned rows
#define BSTRIDE 136   // [k][n] padded
#define STAGES 4

#define CP16(dst, src) asm volatile("cp.async.cg.shared.global [%0], [%1], 16;" :: "r"(dst), "l"(src))

template<bool BIAS, bool RELU, bool RES, bool ROUND>
__global__ void __launch_bounds__(256)
gemm_tf32_kernel(const float* __restrict__ A, const float* __restrict__ B,
                 const float* __restrict__ bias, const float* __restrict__ res,
                 float* __restrict__ C, int M, int N, int K) {
    __shared__ float As[STAGES][128*ASTRIDE];
    __shared__ float Bs[STAGES][16*BSTRIDE];
    const int tid  = threadIdx.x;
    const int wid  = tid >> 5;
    const int lane = tid & 31;
    const int warpM = wid & 3;        // 0..3  -> 32-row slab
    const int warpN = wid >> 2;       // 0..1  -> 64-col slab
    const int gr = lane >> 2;         // 0..7
    const int gc = lane & 3;          // 0..3
    const int m0 = blockIdx.x * 128;  // M fastest: B tile shared by concurrent CTAs
    const int n0 = blockIdx.y * 128;

    float acc[2][8][4];
    #pragma unroll
    for (int mi = 0; mi < 2; mi++)
        #pragma unroll
        for (int ni = 0; ni < 8; ni++)
            #pragma unroll
            for (int j = 0; j < 4; j++) acc[mi][ni][j] = 0.f;

    const int aRow = tid >> 2;          // 0..63
    const int aCol = (tid & 3) << 2;    // 0,4,8,12
    const int bRow = tid >> 5;          // 0..7
    const int bCol = (tid & 31) << 2;   // 0..124

    const float* Ab = A + (long)m0*K;
    const float* Bb = B + n0;
    const int nIter = K >> 4;

    #define ISSUE(it, stg) do {                                            \
        const float* Ag = Ab + ((it) << 4);                                \
        _Pragma("unroll")                                                  \
        for (int r = 0; r < 2; r++) {                                      \
            int row = aRow + r*64;                                         \
            uint32_t d_ = (uint32_t)__cvta_generic_to_shared(              \
                &As[stg][row*ASTRIDE + aCol]);                             \
            CP16(d_, Ag + (long)row*K + aCol);                             \
        }                                                                  \
        const float* Bg = Bb + (long)((it) << 4)*N;                        \
        _Pragma("unroll")                                                  \
        for (int r = 0; r < 2; r++) {                                      \
            int krow = bRow + r*8;                                         \
            uint32_t d_ = (uint32_t)__cvta_generic_to_shared(              \
                &Bs[stg][krow*BSTRIDE + bCol]);                            \
            CP16(d_, Bg + (long)krow*N + bCol);                            \
        }                                                                  \
        asm volatile("cp.async.commit_group;");                            \
    } while (0)

    ISSUE(0, 0); ISSUE(1, 1); ISSUE(2, 2);   // K >= 768 -> nIter >= 48

    for (int it = 0; it < nIter; it++) {
        const int stg = it & (STAGES-1);
        if (it + 2 < nIter)      asm volatile("cp.async.wait_group 2;");
        else if (it + 1 < nIter) asm volatile("cp.async.wait_group 1;");
        else                     asm volatile("cp.async.wait_group 0;");
        __syncthreads();

        #pragma unroll
        for (int kc = 0; kc < 16; kc += 8) {
            uint32_t af[2][4];
            #pragma unroll
            for (int mi = 0; mi < 2; mi++) {
                int row = warpM*32 + mi*16 + gr;
                af[mi][0] = __float_as_uint(As[stg][row*ASTRIDE + kc + gc]);
                af[mi][1] = __float_as_uint(As[stg][(row+8)*ASTRIDE + kc + gc]);
                af[mi][2] = __float_as_uint(As[stg][row*ASTRIDE + kc + gc + 4]);
                af[mi][3] = __float_as_uint(As[stg][(row+8)*ASTRIDE + kc + gc + 4]);
            }
            uint32_t bf[8][2];
            #pragma unroll
            for (int ni = 0; ni < 8; ni++) {
                int col = warpN*64 + ni*8 + gr;
                bf[ni][0] = __float_as_uint(Bs[stg][(kc+gc)*BSTRIDE + col]);
                bf[ni][1] = __float_as_uint(Bs[stg][(kc+gc+4)*BSTRIDE + col]);
            }
            #pragma unroll
            for (int mi = 0; mi < 2; mi++)
                #pragma unroll
                for (int ni = 0; ni < 8; ni++)
                    asm volatile(
                        "mma.sync.aligned.m16n8k8.row.col.f32.tf32.tf32.f32 "
                        "{%0,%1,%2,%3},{%4,%5,%6,%7},{%8,%9},{%0,%1,%2,%3};"
                        : "+f"(acc[mi][ni][0]), "+f"(acc[mi][ni][1]),
                          "+f"(acc[mi][ni][2]), "+f"(acc[mi][ni][3])
                        : "r"(af[mi][0]), "r"(af[mi][1]),
                          "r"(af[mi][2]), "r"(af[mi][3]),
                          "r"(bf[ni][0]), "r"(bf[ni][1]));
        }

        if (it + 3 < nIter) ISSUE(it + 3, (it + 3) & (STAGES-1));
    }
    #undef ISSUE

    // epilogue
    #pragma unroll
    for (int mi = 0; mi < 2; mi++) {
        #pragma unroll
        for (int rr = 0; rr < 2; rr++) {
            long row = m0 + warpM*32 + mi*16 + gr + rr*8;
            #pragma unroll
            for (int ni = 0; ni < 8; ni++) {
                int col = n0 + warpN*64 + ni*8 + gc*2;
                float v0 = acc[mi][ni][rr*2+0];
                float v1 = acc[mi][ni][rr*2+1];
                if (BIAS) { v0 += bias[col]; v1 += bias[col+1]; }
                if (RES)  {
                    float2 rv = *(const float2*)(res + row*N + col);
                    v0 += rv.x; v1 += rv.y;
                }
                if (RELU) { v0 = fmaxf(v0, 0.f); v1 = fmaxf(v1, 0.f); }
                if (ROUND){ v0 = tf32r(v0); v1 = tf32r(v1); }
                float2 ov; ov.x = v0; ov.y = v1;
                *(float2*)(C + row*N + col) = ov;
            }
        }
    }
}

// ---------------- flash attention, 2-way split-K ---------------------------
#define TQ 64
#define TS 16
__global__ void __launch_bounds__(128)
flash_attn_kernel(const float* __restrict__ qkv, float* __restrict__ out) {
    __shared__ float KV[2][2][TS*DH];   // [k/v][half][s*DH+d]
    __shared__ float ml[2][TQ];
    const int q0 = (gridDim.x - 1 - blockIdx.x) * TQ;  // longest first
    const int bh = blockIdx.y;
    const int b  = bh / HH;
    const int h  = bh % HH;
    const int tid  = threadIdx.x;
    const int tq   = tid & 63;
    const int half = tid >> 6;
    const int t = q0 + tq;
    const float* base = qkv + (long)b*TT*QKVN;

    float q[DH];
    {
        const float4* qr = (const float4*)(base + (long)t*QKVN + h*DH);
        #pragma unroll
        for (int j = 0; j < DH/4; j++) {
            float4 v = qr[j];
            q[4*j+0] = v.x; q[4*j+1] = v.y; q[4*j+2] = v.z; q[4*j+3] = v.w;
        }
    }
    float acc[DH];
    #pragma unroll
    for (int j = 0; j < DH; j++) acc[j] = 0.f;
    float m = -1e30f, l = 0.f;

    const int nT = (q0 + TQ) / TS;
    const int nHalf = nT >> 1;
    const int tile0 = half * nHalf;

    for (int jt = 0; jt < nHalf; jt++) {
        const int s0 = (tile0 + jt) * TS;
        __syncthreads();
        #pragma unroll
        for (int i = 0; i < 4; i++) {
            int idx = tq + i*64;
            int s  = idx >> 4;
            int d4 = (idx & 15) << 2;
            const float* kp = base + (long)(s0+s)*QKVN + CC + h*DH + d4;
            *(float4*)&KV[0][half][s*DH + d4] = *(const float4*)kp;
            *(float4*)&KV[1][half][s*DH + d4] = *(const float4*)(kp + CC);
        }
        __syncthreads();

        float sc[TS];
        float tmax = -1e30f;
        #pragma unroll
        for (int s = 0; s < TS; s++) {
            float d0 = 0.f, d1 = 0.f, d2 = 0.f, d3 = 0.f;
            const float* kr = &KV[0][half][s*DH];
            #pragma unroll
            for (int j = 0; j < DH; j += 4) {
                d0 += q[j+0] * kr[j+0];
                d1 += q[j+1] * kr[j+1];
                d2 += q[j+2] * kr[j+2];
                d3 += q[j+3] * kr[j+3];
            }
            float d = (d0 + d1) + (d2 + d3);
            sc[s] = (s0 + s <= t) ? d * 0.125f : -1e30f;
            tmax = fmaxf(tmax, sc[s]);
        }
        if (tmax > -1e29f) {
            float m_new = fmaxf(m, tmax);
            float alpha = __expf(m - m_new);
            l *= alpha;
            #pragma unroll
            for (int j = 0; j < DH; j++) acc[j] *= alpha;
            #pragma unroll
            for (int s = 0; s < TS; s++) {
                float p = (sc[s] > -1e29f) ? __expf(sc[s] - m_new) : 0.f;
                l += p;
                const float* vr = &KV[1][half][s*DH];
                #pragma unroll
                for (int j = 0; j < DH; j++) acc[j] += p * vr[j];
            }
            m = m_new;
        }
    }

    __syncthreads();
    float* xch = (float*)KV;
    if (half == 1) {
        ml[0][tq] = m; ml[1][tq] = l;
        #pragma unroll
        for (int j = 0; j < DH; j++)
            xch[tq*DH + ((j + tq) & 63)] = acc[j];
    }
    __syncthreads();
    if (half == 0) {
        float m1 = ml[0][tq], l1 = ml[1][tq];
        float ms = fmaxf(m, m1);
        float a0 = __expf(m - ms);
        float a1 = __expf(m1 - ms);
        float inv = 1.0f / (l*a0 + l1*a1);
        float* o = out + ((long)b*TT + t)*CC + h*DH;
        #pragma unroll
        for (int j = 0; j < DH; j += 4) {
            float4 v;
            v.x = tf32r((acc[j+0]*a0 + xch[tq*DH + ((j+0+tq)&63)]*a1) * inv);
            v.y = tf32r((acc[j+1]*a0 + xch[tq*DH + ((j+1+tq)&63)]*a1) * inv);
            v.z = tf32r((acc[j+2]*a0 + xch[tq*DH + ((j+2+tq)&63)]*a1) * inv);
            v.w = tf32r((acc[j+3]*a0 + xch[tq*DH + ((j+3+tq)&63)]*a1) * inv);
            *(float4*)(o + j) = v;
        }
    }
}

// ---------------- cross-entropy: single-pass online softmax ----------------
__global__ void loss_rows_kernel(const float* __restrict__ logits,
                                 const int* __restrict__ targets) {
    __shared__ float sm[256], ss[256];
    const int row = blockIdx.x;
    const float* lr = logits + (long)row*VV;
    float m = -1e30f, s = 0.f;
    for (int c = threadIdx.x; c < VV; c += 256) {
        float v = lr[c];
        if (v <= m) s += __expf(v - m);
        else { s = s*__expf(m - v) + 1.f; m = v; }
    }
    sm[threadIdx.x] = m; ss[threadIdx.x] = s;
    __syncthreads();
    for (int o = 128; o > 0; o >>= 1) {
        if (threadIdx.x < o) {
            float m2 = sm[threadIdx.x+o], s2 = ss[threadIdx.x+o];
            float mm = fmaxf(sm[threadIdx.x], m2);
            ss[threadIdx.x] = ss[threadIdx.x]*__expf(sm[threadIdx.x]-mm)
                            + s2*__expf(m2-mm);
            sm[threadIdx.x] = mm;
        }
        __syncthreads();
    }
    if (threadIdx.x == 0) {
        float lse = sm[0] + logf(ss[0]);
        g_rowloss[row] = lse - lr[targets[row]];
    }
}

__global__ void loss_reduce_kernel(float* __restrict__ out) {
    __shared__ float red[256];
    float s = 0.f;
    for (int i = threadIdx.x; i < BT; i += 256) s += g_rowloss[i];
    red[threadIdx.x] = s; __syncthreads();
    for (int o = 128; o > 0; o >>= 1) {
        if (threadIdx.x < o) red[threadIdx.x] += red[threadIdx.x+o];
        __syncthreads();
    }
    if (threadIdx.x == 0) *out = red[0] * (1.0f/BT);
}

// ---------------- driver ----------------------------------------------------
extern "C" void kernel_launch(void* const* d_in, const int* in_sizes, int n_in,
                              void* d_out, int out_size) {
    const int*   idx     = (const int*)  d_in[0];
    const int*   targets = (const int*)  d_in[1];
    const float* tok_emb = (const float*)d_in[2];
    const float* pos_emb = (const float*)d_in[3];
    const float* Wq      = (const float*)d_in[4];
    const float* Wk      = (const float*)d_in[5];
    const float* Wv      = (const float*)d_in[6];
    const float* Wproj   = (const float*)d_in[7];
    const float* bproj   = (const float*)d_in[8];
    const float* ln1_g   = (const float*)d_in[9];
    const float* ln1_b   = (const float*)d_in[10];
    const float* ln2_g   = (const float*)d_in[11];
    const float* ln2_b   = (const float*)d_in[12];
    const float* W1      = (const float*)d_in[13];
    const float* b1      = (const float*)d_in[14];
    const float* W2      = (const float*)d_in[15];
    const float* b2      = (const float*)d_in[16];
    const float* Wlm     = (const float*)d_in[17];
    const float* blm     = (const float*)d_in[18];
    float* out = (float*)d_out;

    float* xp;    cudaGetSymbolAddress((void**)&xp,    g_x);
    float* hp;    cudaGetSymbolAddress((void**)&hp,    g_h);
    float* qkvp;  cudaGetSymbolAddress((void**)&qkvp,  g_qkv);
    float* attnp; cudaGetSymbolAddress((void**)&attnp, g_attn);
    float* hidp;  cudaGetSymbolAddress((void**)&hidp,  g_hid);
    float* wqkvp; cudaGetSymbolAddress((void**)&wqkvp, g_wqkv);
    float* wprojp;cudaGetSymbolAddress((void**)&wprojp,g_wproj);
    float* w1p;   cudaGetSymbolAddress((void**)&w1p,   g_w1);
    float* w2p;   cudaGetSymbolAddress((void**)&w2p,   g_w2);
    float* wlmp;  cudaGetSymbolAddress((void**)&wlmp,  g_wlm);

    pack_qkv_kernel<<<2048, 256>>>(Wq, Wk, Wv);
    round_copy_kernel<<<2048, 256>>>(Wproj, wprojp, (long)LL*CC*CC);
    round_copy_kernel<<<2048, 256>>>(W1,    w1p,    (long)LL*CC*HID);
    round_copy_kernel<<<2048, 256>>>(W2,    w2p,    (long)LL*HID*CC);
    round_copy_kernel<<<4096, 256>>>(Wlm,   wlmp,   (long)CC*VV);
    embed_kernel<<<(BT*CC + 255)/256, 256>>>(idx, tok_emb, pos_emb);

    for (int l = 0; l < LL; l++) {
        layernorm_kernel<<<BT, 256>>>(xp, ln1_g + l*CC, ln1_b + l*CC, hp);

        // qkv = h @ Wqkv[l]    [2048,768]x[768,2304]   (M fastest)
        gemm_tf32_kernel<false,false,false,false><<<dim3(BT/128, QKVN/128), 256>>>(
            hp, wqkvp + (long)l*CC*QKVN, nullptr, nullptr, qkvp, BT, QKVN, CC);

        flash_attn_kernel<<<dim3(TT/TQ, BB*HH), 128>>>(qkvp, attnp);

        // x = x + attn @ Wproj[l] + bproj[l]
        gemm_tf32_kernel<true,false,true,false><<<dim3(BT/128, CC/128), 256>>>(
            attnp, wprojp + (long)l*CC*CC, bproj + l*CC, xp, xp, BT, CC, CC);

        layernorm_kernel<<<BT, 256>>>(xp, ln2_g + l*CC, ln2_b + l*CC, hp);

        // hid = relu(h @ W1[l] + b1[l])  (rounded output: feeds next GEMM)
        gemm_tf32_kernel<true,true,false,true><<<dim3(BT/128, HID/128), 256>>>(
            hp, w1p + (long)l*CC*HID, b1 + (long)l*HID, nullptr, hidp, BT, HID, CC);

        // x = x + hid @ W2[l] + b2[l]
        gemm_tf32_kernel<true,false,true,false><<<dim3(BT/128, CC/128), 256>>>(
            hidp, w2p + (long)l*HID*CC, b2 + l*CC, xp, xp, BT, CC, HID);
    }

    // rounded copy of x for the LM head A-operand
    round_copy_kernel<<<2048, 256>>>(xp, hp, (long)BT*CC);

    // logits = x @ Wlm + blm -> d_out   (M fastest: Wlm read once through L2)
    gemm_tf32_kernel<true,false,false,false><<<dim3(BT/128, VV/128), 256>>>(
        hp, wlmp, blm, nullptr, out, BT, VV, CC);

    loss_rows_kernel<<<BT, 256>>>(out, targets);
    if (out_size >= BT*VV + 1) {
        loss_reduce_kernel<<<1, 256>>>(out + (long)BT*VV);
    } else if (out_size == 1) {
        loss_reduce_kernel<<<1, 256>>>(out);
    }
}